// round 16
// baseline (speedup 1.0000x reference)
#include <cuda_runtime.h>
#include <cuda_fp16.h>
#include <cstdint>

#define D_MODEL 1024
#define NHEADS  16
#define HDIM    64
#define WINDOW  256
#define BATCH   2
#define SEQ     2048
#define MTOT    (BATCH * SEQ)          /* 4096 */
#define QKV_LD  (3 * D_MODEL)          /* 3072 */
#define BHTOT   (BATCH * NHEADS)       /* 32 */

// ---- scratch --------------------------------------------------------------
__device__ __half g_xf[(size_t)MTOT * D_MODEL];
__device__ __half g_wq[(size_t)QKV_LD * D_MODEL];
__device__ __half g_wph[(size_t)D_MODEL * D_MODEL];
// per-head Q/K: [bh][token][e]; V transposed: [bh][e][token]  (plain fp16)
__device__ __half g_q[(size_t)BHTOT * SEQ * HDIM];
__device__ __half g_k[(size_t)BHTOT * SEQ * HDIM];
__device__ __half g_vt[(size_t)BHTOT * HDIM * SEQ];
// attention out (plain fp16) for proj
__device__ __half g_af[(size_t)MTOT * D_MODEL];

// ---- PTX helpers ------------------------------------------------------------
__device__ __forceinline__ uint32_t smem_u32(const void* p) {
    uint32_t a;
    asm("{ .reg .u64 t; cvta.to.shared.u64 t, %1; cvt.u32.u64 %0, t; }" : "=r"(a) : "l"(p));
    return a;
}
__device__ __forceinline__ void cp16(uint32_t dst, const void* src) {
    asm volatile("cp.async.cg.shared.global [%0], [%1], 16;" :: "r"(dst), "l"(src));
}
#define CP_COMMIT()  asm volatile("cp.async.commit_group;" ::: "memory")
#define CP_WAIT(n)   asm volatile("cp.async.wait_group %0;" :: "n"(n) : "memory")

__device__ __forceinline__ void mma_f16(float* d, uint32_t a0, uint32_t a1,
                                        uint32_t a2, uint32_t a3,
                                        uint32_t b0, uint32_t b1) {
    asm("mma.sync.aligned.m16n8k16.row.col.f32.f16.f16.f32 "
        "{%0,%1,%2,%3}, {%4,%5,%6,%7}, {%8,%9}, {%0,%1,%2,%3};"
        : "+f"(d[0]), "+f"(d[1]), "+f"(d[2]), "+f"(d[3])
        : "r"(a0), "r"(a1), "r"(a2), "r"(a3), "r"(b0), "r"(b1));
}
// x4 ldmatrix, non-trans. Lane addressing: row = lane&15, colgroup = lane>>4.
// m0..m3 == {(r,k),(r+8,k),(r,k+8),(r+8,k+8)} — R6-validated mapping.
__device__ __forceinline__ void ldsm_x4(uint32_t* r, uint32_t addr) {
    asm volatile("ldmatrix.sync.aligned.m8n8.x4.shared.b16 {%0,%1,%2,%3}, [%4];"
        : "=r"(r[0]), "=r"(r[1]), "=r"(r[2]), "=r"(r[3]) : "r"(addr));
}

// ---- fused fp32 -> fp16 convert for x, w_qkv, w_proj --------------------------
#define N4X (MTOT * D_MODEL / 4)
#define N4Q (QKV_LD * D_MODEL / 4)
#define N4P (D_MODEL * D_MODEL / 4)

__global__ __launch_bounds__(256)
void cvt_all(const float4* __restrict__ x, const float4* __restrict__ wq,
             const float4* __restrict__ wp,
             __half* __restrict__ xo, __half* __restrict__ wqo,
             __half* __restrict__ wpo)
{
    int i = blockIdx.x * 256 + threadIdx.x;
    const float4* src;
    __half* dst;
    int idx;
    if (i < N4X)            { src = x;  dst = xo;  idx = i; }
    else if (i < N4X + N4Q) { src = wq; dst = wqo; idx = i - N4X; }
    else                    { src = wp; dst = wpo; idx = i - N4X - N4Q; }
    float4 v = src[idx];
    __half2* op = (__half2*)(dst + (size_t)idx * 4);
    op[0] = __half2(__float2half(v.x), __float2half(v.y));
    op[1] = __half2(__float2half(v.z), __float2half(v.w));
}

// ---- QKV GEMM: fp16 1-term, ldmatrix fragments; per-head epilogue ------------
#define BM 128
#define BN 128
#define BK 32
#define SROW 40
#define TILE_E (128 * SROW)
#define GSTAGE_E (2 * TILE_E)
#define GSMEM_SZ 66048                  /* epilogue V stage needs 128*129*4 */

__global__ __launch_bounds__(256, 2)
void gemm_qkv(const __half* __restrict__ A, const __half* __restrict__ W,
              const float* __restrict__ bias,
              __half* __restrict__ q_o, __half* __restrict__ k_o,
              __half* __restrict__ vt_o)
{
    extern __shared__ __half smemh[];
    const int K = D_MODEL;
    const int tid  = threadIdx.x;
    const int lane = tid & 31;
    const int wid  = tid >> 5;
    const int wm   = wid >> 2;
    const int wn   = wid & 3;
    const int tr   = lane >> 2;
    const int tc2  = (lane & 3) * 2;
    const int lrow = lane & 15;          // ldmatrix row within 16
    const int lcol = (lane >> 4) * 8;    // ldmatrix col group
    const int bm   = blockIdx.y * BM;
    const int bn   = blockIdx.x * BN;

    const uint32_t sbase = smem_u32(smemh);

    float acc[4][4][4];
#pragma unroll
    for (int i = 0; i < 4; ++i)
#pragma unroll
        for (int j = 0; j < 4; ++j)
#pragma unroll
            for (int r = 0; r < 4; ++r) acc[i][j][r] = 0.f;

    const __half* srcs[2] = { A, W };
    const int rowoff[2] = { bm, bn };

    auto load_stage = [&](int s, int k0) {
        const uint32_t st = sbase + (uint32_t)(s * GSTAGE_E * 2);
#pragma unroll
        for (int t = 0; t < 2; ++t) {
#pragma unroll
            for (int g2 = 0; g2 < 2; ++g2) {
                const int g = tid + g2 * 256;
                const int row = g >> 2, part = g & 3;
                const uint32_t dst = st + (uint32_t)(t * TILE_E + row * SROW + part * 8) * 2;
                const __half* src = srcs[t] + (size_t)(rowoff[t] + row) * K + k0 + part * 8;
                cp16(dst, src);
            }
        }
    };

    const int KCH = K / BK;
    load_stage(0, 0);
    CP_COMMIT();

    for (int c = 0; c < KCH; ++c) {
        if (c + 1 < KCH) { load_stage((c + 1) & 1, (c + 1) * BK); CP_COMMIT(); CP_WAIT(1); }
        else             { CP_WAIT(0); }
        __syncthreads();

        const uint32_t stg = sbase + (uint32_t)((c & 1) * GSTAGE_E * 2);
        const uint32_t sA = stg;
        const uint32_t sB = stg + TILE_E * 2;

#pragma unroll
        for (int k0 = 0; k0 < BK; k0 += 16) {
            uint32_t ah[4][4], bh[2][4];
#pragma unroll
            for (int mi = 0; mi < 4; ++mi) {
                const uint32_t off =
                    (uint32_t)((wm * 64 + mi * 16 + lrow) * SROW + k0 + lcol) * 2;
                ldsm_x4(ah[mi], sA + off);
            }
#pragma unroll
            for (int p = 0; p < 2; ++p) {
                const uint32_t off =
                    (uint32_t)((wn * 32 + p * 16 + lrow) * SROW + k0 + lcol) * 2;
                ldsm_x4(bh[p], sB + off);
            }
#pragma unroll
            for (int mi = 0; mi < 4; ++mi)
#pragma unroll
                for (int ni = 0; ni < 4; ++ni) {
                    const int p = ni >> 1, od = ni & 1;
                    mma_f16(acc[mi][ni], ah[mi][0], ah[mi][1], ah[mi][2], ah[mi][3],
                            bh[p][0 + od], bh[p][2 + od]);
                }
        }
        __syncthreads();
    }

    // ---- epilogue: plain fp16 Q/K per-head + transposed V ----
    if (bn < 2 * D_MODEL) {
        __half* H = (bn < D_MODEL) ? q_o : k_o;
        const int roff = (bn < D_MODEL) ? bn : bn - D_MODEL;
#pragma unroll
        for (int mi = 0; mi < 4; ++mi) {
            const int r = bm + wm * 64 + mi * 16 + tr;
            const int b = r >> 11, row = r & 2047;
#pragma unroll
            for (int ni = 0; ni < 4; ++ni) {
                const int cl = wn * 32 + ni * 8 + tc2;
                const float b0 = bias[bn + cl], b1 = bias[bn + cl + 1];
                const int cg = roff + cl, hh = cg >> 6, e = cg & 63;
                const size_t base =
                    (((size_t)b * NHEADS + hh) * SEQ + row) * HDIM + e;
                __half2 u01(__float2half(acc[mi][ni][0] + b0),
                            __float2half(acc[mi][ni][1] + b1));
                __half2 u23(__float2half(acc[mi][ni][2] + b0),
                            __float2half(acc[mi][ni][3] + b1));
                *(__half2*)(H + base)            = u01;
                *(__half2*)(H + base + 8 * HDIM) = u23;
            }
        }
    } else {
        float* sf = (float*)smemh;
#pragma unroll
        for (int mi = 0; mi < 4; ++mi) {
            const int r0 = wm * 64 + mi * 16 + tr;
#pragma unroll
            for (int ni = 0; ni < 4; ++ni) {
                const int cl = wn * 32 + ni * 8 + tc2;
                const float b0 = bias[bn + cl], b1 = bias[bn + cl + 1];
                sf[r0 * 129 + cl]           = acc[mi][ni][0] + b0;
                sf[r0 * 129 + cl + 1]       = acc[mi][ni][1] + b1;
                sf[(r0 + 8) * 129 + cl]     = acc[mi][ni][2] + b0;
                sf[(r0 + 8) * 129 + cl + 1] = acc[mi][ni][3] + b1;
            }
        }
        __syncthreads();
        for (int idx = tid; idx < 128 * 64; idx += 256) {
            const int el = idx >> 6, rp = idx & 63;
            const float f0 = sf[(2 * rp) * 129 + el];
            const float f1 = sf[(2 * rp + 1) * 129 + el];
            const int cg = bn - 2 * D_MODEL + el, hh = cg >> 6, e = cg & 63;
            const int rg = bm + 2 * rp, b = rg >> 11, row = rg & 2047;
            const size_t base = (((size_t)b * NHEADS + hh) * HDIM + e) * SEQ + row;
            *(__half2*)(vt_o + base) = __half2(__float2half(f0), __float2half(f1));
        }
    }
}

// ---- swa: unchanged from R15 --------------------------------------------------
#define SROW2 72
#define QT (64 * SROW2)
#define SWA_SMEM (5 * QT * 2)

__global__ __launch_bounds__(128, 2)
void swa_tensor(const __half* __restrict__ q_g, const __half* __restrict__ k_g,
                const __half* __restrict__ vt_g, __half* __restrict__ af)
{
    extern __shared__ __half smf[];
    const int tid = threadIdx.x, lane = tid & 31, w = tid >> 5;
    const int bh = blockIdx.y;
    const int q0 = blockIdx.x * 64;
    const int tr = lane >> 2, tc2 = (lane & 3) * 2;

    const uint32_t sQ = smem_u32(smf);

    const size_t qkbase = (size_t)bh * SEQ * HDIM;
    const size_t vbase  = (size_t)bh * HDIM * SEQ;

    auto load_qk = [&](uint32_t sdst, const __half* src) {
#pragma unroll
        for (int it = 0; it < 4; ++it) {
            const int g = it * 128 + tid;
            const int row = g >> 3, ch = g & 7;
            cp16(sdst + (uint32_t)(row * SROW2 + ch * 8) * 2,
                 src + (size_t)row * HDIM + ch * 8);
        }
    };
    auto load_vt = [&](uint32_t sdst, const __half* src) {
#pragma unroll
        for (int it = 0; it < 4; ++it) {
            const int g = it * 128 + tid;
            const int row = g >> 3, ch = g & 7;
            cp16(sdst + (uint32_t)(row * SROW2 + ch * 8) * 2,
                 src + (size_t)row * SEQ + ch * 8);
        }
    };
    auto issue_stage = [&](int s, int j0) {
        const uint32_t st = sQ + (uint32_t)((1 + 2 * s) * QT) * 2;
        load_qk(st,          k_g + qkbase + (size_t)j0 * HDIM);
        load_vt(st + QT * 2, vt_g + vbase + j0);
    };

    const int kt0 = max(0, (int)blockIdx.x - 4);
    const int kt1 = blockIdx.x;

    load_qk(sQ, q_g + qkbase + (size_t)q0 * HDIM);
    issue_stage(0, kt0 * 64);
    CP_COMMIT();

    uint32_t qf[4][4];
    float o[8][4];
#pragma unroll
    for (int ni = 0; ni < 8; ++ni)
#pragma unroll
        for (int j = 0; j < 4; ++j) o[ni][j] = 0.f;
    float m0 = -1e30f, m1 = -1e30f, l0 = 0.f, l1 = 0.f;
    const int i0 = q0 + w * 16 + tr;
    const int i1 = i0 + 8;

    for (int kt = kt0; kt <= kt1; ++kt) {
        const int s = (kt - kt0) & 1;
        if (kt + 1 <= kt1) { issue_stage(s ^ 1, (kt + 1) * 64); CP_COMMIT(); CP_WAIT(1); }
        else               { CP_WAIT(0); }
        __syncthreads();

        if (kt == kt0) {
            const __half* Q = smf;
#pragma unroll
            for (int ks = 0; ks < 4; ++ks) {
                const int base = (w * 16 + tr) * SROW2 + ks * 16 + tc2;
                qf[ks][0] = *(const uint32_t*)(Q + base);
                qf[ks][1] = *(const uint32_t*)(Q + base + 8 * SROW2);
                qf[ks][2] = *(const uint32_t*)(Q + base + 8);
                qf[ks][3] = *(const uint32_t*)(Q + base + 8 * SROW2 + 8);
            }
        }

        const __half* Kt = smf + (1 + 2 * s) * QT;
        const __half* Vt = Kt + QT;
        const int j0 = kt * 64;

        float sacc[8][4];
#pragma unroll
        for (int ni = 0; ni < 8; ++ni)
#pragma unroll
            for (int j = 0; j < 4; ++j) sacc[ni][j] = 0.f;
#pragma unroll
        for (int ks = 0; ks < 4; ++ks) {
            uint32_t kb[8][2];
#pragma unroll
            for (int ni = 0; ni < 8; ++ni) {
                const int base = (ni * 8 + tr) * SROW2 + ks * 16 + tc2;
                kb[ni][0] = *(const uint32_t*)(Kt + base);
                kb[ni][1] = *(const uint32_t*)(Kt + base + 8);
            }
#pragma unroll
            for (int ni = 0; ni < 8; ++ni)
                mma_f16(sacc[ni], qf[ks][0], qf[ks][1], qf[ks][2], qf[ks][3],
                        kb[ni][0], kb[ni][1]);
        }

        float tmax0 = -1e30f, tmax1 = -1e30f;
#pragma unroll
        for (int ni = 0; ni < 8; ++ni) {
            const int ja = j0 + ni * 8 + tc2, jb = ja + 1;
            sacc[ni][0] = (ja <= i0 && (i0 - ja) < WINDOW) ? sacc[ni][0] * 0.125f : -1e30f;
            sacc[ni][1] = (jb <= i0 && (i0 - jb) < WINDOW) ? sacc[ni][1] * 0.125f : -1e30f;
            sacc[ni][2] = (ja <= i1 && (i1 - ja) < WINDOW) ? sacc[ni][2] * 0.125f : -1e30f;
            sacc[ni][3] = (jb <= i1 && (i1 - jb) < WINDOW) ? sacc[ni][3] * 0.125f : -1e30f;
            tmax0 = fmaxf(tmax0, fmaxf(sacc[ni][0], sacc[ni][1]));
            tmax1 = fmaxf(tmax1, fmaxf(sacc[ni][2], sacc[ni][3]));
        }
        tmax0 = fmaxf(tmax0, __shfl_xor_sync(0xffffffff, tmax0, 1));
        tmax0 = fmaxf(tmax0, __shfl_xor_sync(0xffffffff, tmax0, 2));
        tmax1 = fmaxf(tmax1, __shfl_xor_sync(0xffffffff, tmax1, 1));
        tmax1 = fmaxf(tmax1, __shfl_xor_sync(0xffffffff, tmax1, 2));

        const float mn0 = fmaxf(m0, tmax0), mn1 = fmaxf(m1, tmax1);
        const float sc0 = __expf(m0 - mn0), sc1 = __expf(m1 - mn1);
        m0 = mn0; m1 = mn1;

        float rs0 = 0.f, rs1 = 0.f;
        uint32_t ph[8][2], pl[8][2];
#pragma unroll
        for (int ni = 0; ni < 8; ++ni) {
            float p0 = __expf(sacc[ni][0] - mn0);
            float p1 = __expf(sacc[ni][1] - mn0);
            float p2 = __expf(sacc[ni][2] - mn1);
            float p3 = __expf(sacc[ni][3] - mn1);
            rs0 += p0 + p1; rs1 += p2 + p3;
            __half b0 = __float2half(p0), b1 = __float2half(p1);
            __half b2 = __float2half(p2), b3 = __float2half(p3);
            __half2 t01(b0, b1), t23(b2, b3);
            __half2 w01(__float2half(p0 - __half2float(b0)),
                        __float2half(p1 - __half2float(b1)));
            __half2 w23(__float2half(p2 - __half2float(b2)),
                        __float2half(p3 - __half2float(b3)));
            ph[ni][0] = *(uint32_t*)&t01;
            ph[ni][1] = *(uint32_t*)&t23;
            pl[ni][0] = *(uint32_t*)&w01;
            pl[ni][1] = *(uint32_t*)&w23;
        }
        rs0 += __shfl_xor_sync(0xffffffff, rs0, 1);
        rs0 += __shfl_xor_sync(0xffffffff, rs0, 2);
        rs1 += __shfl_xor_sync(0xffffffff, rs1, 1);
        rs1 += __shfl_xor_sync(0xffffffff, rs1, 2);
        l0 = l0 * sc0 + rs0;
        l1 = l1 * sc1 + rs1;

#pragma unroll
        for (int ni = 0; ni < 8; ++ni) {
            o[ni][0] *= sc0; o[ni][1] *= sc0;
            o[ni][2] *= sc1; o[ni][3] *= sc1;
        }

#pragma unroll
        for (int ks = 0; ks < 4; ++ks) {
            uint32_t vb[8][2];
#pragma unroll
            for (int ni = 0; ni < 8; ++ni) {
                const int base = (ni * 8 + tr) * SROW2 + ks * 16 + tc2;
                vb[ni][0] = *(const uint32_t*)(Vt + base);
                vb[ni][1] = *(const uint32_t*)(Vt + base + 8);
            }
#pragma unroll
            for (int ni = 0; ni < 8; ++ni)
                mma_f16(o[ni], ph[2*ks][0], ph[2*ks][1], ph[2*ks+1][0], ph[2*ks+1][1],
                        vb[ni][0], vb[ni][1]);
#pragma unroll
            for (int ni = 0; ni < 8; ++ni)
                mma_f16(o[ni], pl[2*ks][0], pl[2*ks][1], pl[2*ks+1][0], pl[2*ks+1][1],
                        vb[ni][0], vb[ni][1]);
        }
        __syncthreads();
    }

    const int b = bh >> 4, h = bh & 15;
    const float inv0 = 1.f / l0, inv1 = 1.f / l1;
    const size_t t0 = (size_t)(b * SEQ + i0) * D_MODEL + (size_t)h * HDIM;
    const size_t t1 = (size_t)(b * SEQ + i1) * D_MODEL + (size_t)h * HDIM;
#pragma unroll
    for (int ni = 0; ni < 8; ++ni) {
        const int c = ni * 8 + tc2;
        *(__half2*)(af + t0 + c) = __half2(__float2half(o[ni][0] * inv0),
                                           __float2half(o[ni][1] * inv0));
        *(__half2*)(af + t1 + c) = __half2(__float2half(o[ni][2] * inv1),
                                           __float2half(o[ni][3] * inv1));
    }
}

// ---- proj GEMM: fp16 1-term, ldmatrix fragments --------------------------------
__global__ __launch_bounds__(256, 2)
void gemm_proj(const __half* __restrict__ A, const __half* __restrict__ W,
               const float* __restrict__ bias, float* __restrict__ C,
               int M, int N, int K)
{
    extern __shared__ __half smemh[];
    const int tid  = threadIdx.x;
    const int lane = tid & 31;
    const int wid  = tid >> 5;
    const int wm   = wid >> 2;
    const int wn   = wid & 3;
    const int tr   = lane >> 2;
    const int tc2  = (lane & 3) * 2;
    const int lrow = lane & 15;
    const int lcol = (lane >> 4) * 8;
    const int bm   = blockIdx.y * BM;
    const int bn   = blockIdx.x * BN;

    const uint32_t sbase = smem_u32(smemh);

    float acc[4][4][4];
#pragma unroll
    for (int i = 0; i < 4; ++i)
#pragma unroll
        for (int j = 0; j < 4; ++j)
#pragma unroll
            for (int r = 0; r < 4; ++r) acc[i][j][r] = 0.f;

    const __half* srcs[2] = { A, W };
    const int rowoff[2] = { bm, bn };

    auto load_stage = [&](int s, int k0) {
        const uint32_t st = sbase + (uint32_t)(s * GSTAGE_E * 2);
#pragma unroll
        for (int t = 0; t < 2; ++t) {
#pragma unroll
            for (int g2 = 0; g2 < 2; ++g2) {
                const int g = tid + g2 * 256;
                const int row = g >> 2, part = g & 3;
                const uint32_t dst = st + (uint32_t)(t * TILE_E + row * SROW + part * 8) * 2;
                const __half* src = srcs[t] + (size_t)(rowoff[t] + row) * K + k0 + part * 8;
                cp16(dst, src);
            }
        }
    };

    const int KCH = K / BK;
    load_stage(0, 0);
    CP_COMMIT();

    for (int c = 0; c < KCH; ++c) {
        if (c + 1 < KCH) { load_stage((c + 1) & 1, (c + 1) * BK); CP_COMMIT(); CP_WAIT(1); }
        else             { CP_WAIT(0); }
        __syncthreads();

        const uint32_t stg = sbase + (uint32_t)((c & 1) * GSTAGE_E * 2);
        const uint32_t sA = stg;
        const uint32_t sB = stg + TILE_E * 2;

#pragma unroll
        for (int k0 = 0; k0 < BK; k0 += 16) {
            uint32_t ah[4][4], bh[2][4];
#pragma unroll
            for (int mi = 0; mi < 4; ++mi) {
                const uint32_t off =
                    (uint32_t)((wm * 64 + mi * 16 + lrow) * SROW + k0 + lcol) * 2;
                ldsm_x4(ah[mi], sA + off);
            }
#pragma unroll
            for (int p = 0; p < 2; ++p) {
                const uint32_t off =
                    (uint32_t)((wn * 32 + p * 16 + lrow) * SROW + k0 + lcol) * 2;
                ldsm_x4(bh[p], sB + off);
            }
#pragma unroll
            for (int mi = 0; mi < 4; ++mi)
#pragma unroll
                for (int ni = 0; ni < 4; ++ni) {
                    const int p = ni >> 1, od = ni & 1;
                    mma_f16(acc[mi][ni], ah[mi][0], ah[mi][1], ah[mi][2], ah[mi][3],
                            bh[p][0 + od], bh[p][2 + od]);
                }
        }
        __syncthreads();
    }

#pragma unroll
    for (int mi = 0; mi < 4; ++mi) {
        const int r = bm + wm * 64 + mi * 16 + tr;
#pragma unroll
        for (int ni = 0; ni < 4; ++ni) {
            const int cidx = bn + wn * 32 + ni * 8 + tc2;
            const float b0 = bias[cidx], b1 = bias[cidx + 1];
            float2 v0 = make_float2(acc[mi][ni][0] + b0, acc[mi][ni][1] + b1);
            float2 v1 = make_float2(acc[mi][ni][2] + b0, acc[mi][ni][3] + b1);
            *(float2*)(C + (size_t)r * N + cidx)       = v0;
            *(float2*)(C + (size_t)(r + 8) * N + cidx) = v1;
        }
    }
}

// ---------------------------------------------------------------------------
extern "C" void kernel_launch(void* const* d_in, const int* in_sizes, int n_in,
                              void* d_out, int out_size)
{
    const float* x      = (const float*)d_in[0];
    const float* w_qkv  = (const float*)d_in[1];
    const float* b_qkv  = (const float*)d_in[2];
    const float* w_proj = (const float*)d_in[3];
    const float* b_proj = (const float*)d_in[4];
    float* out = (float*)d_out;

    __half *xf, *wq, *wph, *af, *q, *k, *vt;
    cudaGetSymbolAddress((void**)&xf, g_xf);
    cudaGetSymbolAddress((void**)&wq, g_wq);
    cudaGetSymbolAddress((void**)&wph, g_wph);
    cudaGetSymbolAddress((void**)&q, g_q);
    cudaGetSymbolAddress((void**)&k, g_k);
    cudaGetSymbolAddress((void**)&vt, g_vt);
    cudaGetSymbolAddress((void**)&af, g_af);

    cudaFuncSetAttribute(gemm_qkv,
                         cudaFuncAttributeMaxDynamicSharedMemorySize, GSMEM_SZ);
    cudaFuncSetAttribute(swa_tensor,
                         cudaFuncAttributeMaxDynamicSharedMemorySize, SWA_SMEM);
    cudaFuncSetAttribute(gemm_proj,
                         cudaFuncAttributeMaxDynamicSharedMemorySize, GSMEM_SZ);

    // fused input conversion (one launch)
    cvt_all<<<(N4X + N4Q + N4P) / 256, 256>>>(
        (const float4*)x, (const float4*)w_qkv, (const float4*)w_proj,
        xf, wq, wph);

    // 1) QKV projection (fp16 1-term, ldmatrix) -> per-head fp16 Q,K + V^T
    gemm_qkv<<<dim3(QKV_LD / BN, MTOT / BM), 256, GSMEM_SZ>>>(
        xf, wq, b_qkv, q, k, vt);

    // 2) sliding-window attention -> plain fp16
    swa_tensor<<<dim3(SEQ / 64, BHTOT), 128, SWA_SMEM>>>(q, k, vt, af);

    // 3) output projection (fp16 1-term, ldmatrix)
    gemm_proj<<<dim3(D_MODEL / BN, MTOT / BM), 256, GSMEM_SZ>>>(
        af, wph, b_proj, out, MTOT, D_MODEL, D_MODEL);
}

// round 17
// speedup vs baseline: 1.0110x; 1.0110x over previous
#include <cuda_runtime.h>
#include <cuda_fp16.h>
#include <cstdint>

#define D_MODEL 1024
#define NHEADS  16
#define HDIM    64
#define WINDOW  256
#define BATCH   2
#define SEQ     2048
#define MTOT    (BATCH * SEQ)          /* 4096 */
#define QKV_LD  (3 * D_MODEL)          /* 3072 */
#define BHTOT   (BATCH * NHEADS)       /* 32 */

// ---- scratch --------------------------------------------------------------
__device__ __half g_xf[(size_t)MTOT * D_MODEL];
__device__ __half g_wq[(size_t)QKV_LD * D_MODEL];
__device__ __half g_wph[(size_t)D_MODEL * D_MODEL];
// per-head Q/K: [bh][token][e]; V transposed: [bh][e][token]  (plain fp16)
__device__ __half g_q[(size_t)BHTOT * SEQ * HDIM];
__device__ __half g_k[(size_t)BHTOT * SEQ * HDIM];
__device__ __half g_vt[(size_t)BHTOT * HDIM * SEQ];
// attention out (plain fp16) for proj
__device__ __half g_af[(size_t)MTOT * D_MODEL];

// ---- PTX helpers ------------------------------------------------------------
__device__ __forceinline__ uint32_t smem_u32(const void* p) {
    uint32_t a;
    asm("{ .reg .u64 t; cvta.to.shared.u64 t, %1; cvt.u32.u64 %0, t; }" : "=r"(a) : "l"(p));
    return a;
}
__device__ __forceinline__ void cp16(uint32_t dst, const void* src) {
    asm volatile("cp.async.cg.shared.global [%0], [%1], 16;" :: "r"(dst), "l"(src));
}
#define CP_COMMIT()  asm volatile("cp.async.commit_group;" ::: "memory")
#define CP_WAIT(n)   asm volatile("cp.async.wait_group %0;" :: "n"(n) : "memory")

__device__ __forceinline__ void mma_f16(float* d, uint32_t a0, uint32_t a1,
                                        uint32_t a2, uint32_t a3,
                                        uint32_t b0, uint32_t b1) {
    asm("mma.sync.aligned.m16n8k16.row.col.f32.f16.f16.f32 "
        "{%0,%1,%2,%3}, {%4,%5,%6,%7}, {%8,%9}, {%0,%1,%2,%3};"
        : "+f"(d[0]), "+f"(d[1]), "+f"(d[2]), "+f"(d[3])
        : "r"(a0), "r"(a1), "r"(a2), "r"(a3), "r"(b0), "r"(b1));
}

// ---- fused fp32 -> fp16 convert for x, w_qkv, w_proj --------------------------
#define N4X (MTOT * D_MODEL / 4)
#define N4Q (QKV_LD * D_MODEL / 4)
#define N4P (D_MODEL * D_MODEL / 4)

__global__ __launch_bounds__(256)
void cvt_all(const float4* __restrict__ x, const float4* __restrict__ wq,
             const float4* __restrict__ wp,
             __half* __restrict__ xo, __half* __restrict__ wqo,
             __half* __restrict__ wpo)
{
    int i = blockIdx.x * 256 + threadIdx.x;
    const float4* src;
    __half* dst;
    int idx;
    if (i < N4X)            { src = x;  dst = xo;  idx = i; }
    else if (i < N4X + N4Q) { src = wq; dst = wqo; idx = i - N4X; }
    else                    { src = wp; dst = wpo; idx = i - N4X - N4Q; }
    float4 v = src[idx];
    __half2* op = (__half2*)(dst + (size_t)idx * 4);
    op[0] = __half2(__float2half(v.x), __float2half(v.y));
    op[1] = __half2(__float2half(v.z), __float2half(v.w));
}

// ---- QKV GEMM: fp16 1-term, 3-stage cp.async pipeline ------------------------
#define BM 128
#define BN 128
#define BK 32
#define SROW 40
#define TILE_E (128 * SROW)
#define GSTAGE_E (2 * TILE_E)
#define GSMEM_SZ 66048                  /* >= 3*GSTAGE_E*2 = 61440; V stage 66048 */

__global__ __launch_bounds__(256, 2)
void gemm_qkv(const __half* __restrict__ A, const __half* __restrict__ W,
              const float* __restrict__ bias,
              __half* __restrict__ q_o, __half* __restrict__ k_o,
              __half* __restrict__ vt_o)
{
    extern __shared__ __half smemh[];
    const int K = D_MODEL;
    const int tid  = threadIdx.x;
    const int lane = tid & 31;
    const int wid  = tid >> 5;
    const int wm   = wid >> 2;
    const int wn   = wid & 3;
    const int tr   = lane >> 2;
    const int tc2  = (lane & 3) * 2;
    const int bm   = blockIdx.y * BM;
    const int bn   = blockIdx.x * BN;

    const uint32_t sbase = smem_u32(smemh);

    float acc[4][4][4];
#pragma unroll
    for (int i = 0; i < 4; ++i)
#pragma unroll
        for (int j = 0; j < 4; ++j)
#pragma unroll
            for (int r = 0; r < 4; ++r) acc[i][j][r] = 0.f;

    const __half* srcs[2] = { A, W };
    const int rowoff[2] = { bm, bn };

    auto load_stage = [&](int s, int k0) {
        const uint32_t st = sbase + (uint32_t)(s * GSTAGE_E * 2);
#pragma unroll
        for (int t = 0; t < 2; ++t) {
#pragma unroll
            for (int g2 = 0; g2 < 2; ++g2) {
                const int g = tid + g2 * 256;
                const int row = g >> 2, part = g & 3;
                const uint32_t dst = st + (uint32_t)(t * TILE_E + row * SROW + part * 8) * 2;
                const __half* src = srcs[t] + (size_t)(rowoff[t] + row) * K + k0 + part * 8;
                cp16(dst, src);
            }
        }
    };

    const int KCH = K / BK;              /* 32 */
    load_stage(0, 0);
    CP_COMMIT();
    load_stage(1, BK);
    CP_COMMIT();

    int s = 0;
    for (int c = 0; c < KCH; ++c) {
        if (c + 2 < KCH) {
            const int sn = (s + 2 >= 3) ? s - 1 : s + 2;
            load_stage(sn, (c + 2) * BK);
            CP_COMMIT();
            CP_WAIT(2);
        } else if (c + 1 < KCH) {
            CP_WAIT(1);
        } else {
            CP_WAIT(0);
        }
        __syncthreads();

        const __half* stg = smemh + s * GSTAGE_E;
        const __half* Ah = stg;
        const __half* Bh = stg + TILE_E;

#pragma unroll
        for (int k0 = 0; k0 < BK; k0 += 16) {
            uint32_t ah[4][4], bh[4][2];
#pragma unroll
            for (int mi = 0; mi < 4; ++mi) {
                const int base = (wm * 64 + mi * 16 + tr) * SROW + k0 + tc2;
                ah[mi][0] = *(const uint32_t*)(Ah + base);
                ah[mi][1] = *(const uint32_t*)(Ah + base + 8 * SROW);
                ah[mi][2] = *(const uint32_t*)(Ah + base + 8);
                ah[mi][3] = *(const uint32_t*)(Ah + base + 8 * SROW + 8);
            }
#pragma unroll
            for (int ni = 0; ni < 4; ++ni) {
                const int base = (wn * 32 + ni * 8 + tr) * SROW + k0 + tc2;
                bh[ni][0] = *(const uint32_t*)(Bh + base);
                bh[ni][1] = *(const uint32_t*)(Bh + base + 8);
            }
#pragma unroll
            for (int mi = 0; mi < 4; ++mi)
#pragma unroll
                for (int ni = 0; ni < 4; ++ni)
                    mma_f16(acc[mi][ni], ah[mi][0], ah[mi][1], ah[mi][2], ah[mi][3],
                            bh[ni][0], bh[ni][1]);
        }
        __syncthreads();
        s = (s == 2) ? 0 : s + 1;
    }

    // ---- epilogue: plain fp16 Q/K per-head + transposed V ----
    if (bn < 2 * D_MODEL) {
        __half* H = (bn < D_MODEL) ? q_o : k_o;
        const int roff = (bn < D_MODEL) ? bn : bn - D_MODEL;
#pragma unroll
        for (int mi = 0; mi < 4; ++mi) {
            const int r = bm + wm * 64 + mi * 16 + tr;
            const int b = r >> 11, row = r & 2047;
#pragma unroll
            for (int ni = 0; ni < 4; ++ni) {
                const int cl = wn * 32 + ni * 8 + tc2;
                const float b0 = bias[bn + cl], b1 = bias[bn + cl + 1];
                const int cg = roff + cl, hh = cg >> 6, e = cg & 63;
                const size_t base =
                    (((size_t)b * NHEADS + hh) * SEQ + row) * HDIM + e;
                __half2 u01(__float2half(acc[mi][ni][0] + b0),
                            __float2half(acc[mi][ni][1] + b1));
                __half2 u23(__float2half(acc[mi][ni][2] + b0),
                            __float2half(acc[mi][ni][3] + b1));
                *(__half2*)(H + base)            = u01;
                *(__half2*)(H + base + 8 * HDIM) = u23;
            }
        }
    } else {
        float* sf = (float*)smemh;
#pragma unroll
        for (int mi = 0; mi < 4; ++mi) {
            const int r0 = wm * 64 + mi * 16 + tr;
#pragma unroll
            for (int ni = 0; ni < 4; ++ni) {
                const int cl = wn * 32 + ni * 8 + tc2;
                const float b0 = bias[bn + cl], b1 = bias[bn + cl + 1];
                sf[r0 * 129 + cl]           = acc[mi][ni][0] + b0;
                sf[r0 * 129 + cl + 1]       = acc[mi][ni][1] + b1;
                sf[(r0 + 8) * 129 + cl]     = acc[mi][ni][2] + b0;
                sf[(r0 + 8) * 129 + cl + 1] = acc[mi][ni][3] + b1;
            }
        }
        __syncthreads();
        for (int idx = tid; idx < 128 * 64; idx += 256) {
            const int el = idx >> 6, rp = idx & 63;
            const float f0 = sf[(2 * rp) * 129 + el];
            const float f1 = sf[(2 * rp + 1) * 129 + el];
            const int cg = bn - 2 * D_MODEL + el, hh = cg >> 6, e = cg & 63;
            const int rg = bm + 2 * rp, b = rg >> 11, row = rg & 2047;
            const size_t base = (((size_t)b * NHEADS + hh) * HDIM + e) * SEQ + row;
            *(__half2*)(vt_o + base) = __half2(__float2half(f0), __float2half(f1));
        }
    }
}

// ---- swa: unchanged from R15 --------------------------------------------------
#define SROW2 72
#define QT (64 * SROW2)
#define SWA_SMEM (5 * QT * 2)

__global__ __launch_bounds__(128, 2)
void swa_tensor(const __half* __restrict__ q_g, const __half* __restrict__ k_g,
                const __half* __restrict__ vt_g, __half* __restrict__ af)
{
    extern __shared__ __half smf[];
    const int tid = threadIdx.x, lane = tid & 31, w = tid >> 5;
    const int bh = blockIdx.y;
    const int q0 = blockIdx.x * 64;
    const int tr = lane >> 2, tc2 = (lane & 3) * 2;

    const uint32_t sQ = smem_u32(smf);

    const size_t qkbase = (size_t)bh * SEQ * HDIM;
    const size_t vbase  = (size_t)bh * HDIM * SEQ;

    auto load_qk = [&](uint32_t sdst, const __half* src) {
#pragma unroll
        for (int it = 0; it < 4; ++it) {
            const int g = it * 128 + tid;
            const int row = g >> 3, ch = g & 7;
            cp16(sdst + (uint32_t)(row * SROW2 + ch * 8) * 2,
                 src + (size_t)row * HDIM + ch * 8);
        }
    };
    auto load_vt = [&](uint32_t sdst, const __half* src) {
#pragma unroll
        for (int it = 0; it < 4; ++it) {
            const int g = it * 128 + tid;
            const int row = g >> 3, ch = g & 7;
            cp16(sdst + (uint32_t)(row * SROW2 + ch * 8) * 2,
                 src + (size_t)row * SEQ + ch * 8);
        }
    };
    auto issue_stage = [&](int s, int j0) {
        const uint32_t st = sQ + (uint32_t)((1 + 2 * s) * QT) * 2;
        load_qk(st,          k_g + qkbase + (size_t)j0 * HDIM);
        load_vt(st + QT * 2, vt_g + vbase + j0);
    };

    const int kt0 = max(0, (int)blockIdx.x - 4);
    const int kt1 = blockIdx.x;

    load_qk(sQ, q_g + qkbase + (size_t)q0 * HDIM);
    issue_stage(0, kt0 * 64);
    CP_COMMIT();

    uint32_t qf[4][4];
    float o[8][4];
#pragma unroll
    for (int ni = 0; ni < 8; ++ni)
#pragma unroll
        for (int j = 0; j < 4; ++j) o[ni][j] = 0.f;
    float m0 = -1e30f, m1 = -1e30f, l0 = 0.f, l1 = 0.f;
    const int i0 = q0 + w * 16 + tr;
    const int i1 = i0 + 8;

    for (int kt = kt0; kt <= kt1; ++kt) {
        const int s = (kt - kt0) & 1;
        if (kt + 1 <= kt1) { issue_stage(s ^ 1, (kt + 1) * 64); CP_COMMIT(); CP_WAIT(1); }
        else               { CP_WAIT(0); }
        __syncthreads();

        if (kt == kt0) {
            const __half* Q = smf;
#pragma unroll
            for (int ks = 0; ks < 4; ++ks) {
                const int base = (w * 16 + tr) * SROW2 + ks * 16 + tc2;
                qf[ks][0] = *(const uint32_t*)(Q + base);
                qf[ks][1] = *(const uint32_t*)(Q + base + 8 * SROW2);
                qf[ks][2] = *(const uint32_t*)(Q + base + 8);
                qf[ks][3] = *(const uint32_t*)(Q + base + 8 * SROW2 + 8);
            }
        }

        const __half* Kt = smf + (1 + 2 * s) * QT;
        const __half* Vt = Kt + QT;
        const int j0 = kt * 64;

        float sacc[8][4];
#pragma unroll
        for (int ni = 0; ni < 8; ++ni)
#pragma unroll
            for (int j = 0; j < 4; ++j) sacc[ni][j] = 0.f;
#pragma unroll
        for (int ks = 0; ks < 4; ++ks) {
            uint32_t kb[8][2];
#pragma unroll
            for (int ni = 0; ni < 8; ++ni) {
                const int base = (ni * 8 + tr) * SROW2 + ks * 16 + tc2;
                kb[ni][0] = *(const uint32_t*)(Kt + base);
                kb[ni][1] = *(const uint32_t*)(Kt + base + 8);
            }
#pragma unroll
            for (int ni = 0; ni < 8; ++ni)
                mma_f16(sacc[ni], qf[ks][0], qf[ks][1], qf[ks][2], qf[ks][3],
                        kb[ni][0], kb[ni][1]);
        }

        float tmax0 = -1e30f, tmax1 = -1e30f;
#pragma unroll
        for (int ni = 0; ni < 8; ++ni) {
            const int ja = j0 + ni * 8 + tc2, jb = ja + 1;
            sacc[ni][0] = (ja <= i0 && (i0 - ja) < WINDOW) ? sacc[ni][0] * 0.125f : -1e30f;
            sacc[ni][1] = (jb <= i0 && (i0 - jb) < WINDOW) ? sacc[ni][1] * 0.125f : -1e30f;
            sacc[ni][2] = (ja <= i1 && (i1 - ja) < WINDOW) ? sacc[ni][2] * 0.125f : -1e30f;
            sacc[ni][3] = (jb <= i1 && (i1 - jb) < WINDOW) ? sacc[ni][3] * 0.125f : -1e30f;
            tmax0 = fmaxf(tmax0, fmaxf(sacc[ni][0], sacc[ni][1]));
            tmax1 = fmaxf(tmax1, fmaxf(sacc[ni][2], sacc[ni][3]));
        }
        tmax0 = fmaxf(tmax0, __shfl_xor_sync(0xffffffff, tmax0, 1));
        tmax0 = fmaxf(tmax0, __shfl_xor_sync(0xffffffff, tmax0, 2));
        tmax1 = fmaxf(tmax1, __shfl_xor_sync(0xffffffff, tmax1, 1));
        tmax1 = fmaxf(tmax1, __shfl_xor_sync(0xffffffff, tmax1, 2));

        const float mn0 = fmaxf(m0, tmax0), mn1 = fmaxf(m1, tmax1);
        const float sc0 = __expf(m0 - mn0), sc1 = __expf(m1 - mn1);
        m0 = mn0; m1 = mn1;

        float rs0 = 0.f, rs1 = 0.f;
        uint32_t ph[8][2], pl[8][2];
#pragma unroll
        for (int ni = 0; ni < 8; ++ni) {
            float p0 = __expf(sacc[ni][0] - mn0);
            float p1 = __expf(sacc[ni][1] - mn0);
            float p2 = __expf(sacc[ni][2] - mn1);
            float p3 = __expf(sacc[ni][3] - mn1);
            rs0 += p0 + p1; rs1 += p2 + p3;
            __half b0 = __float2half(p0), b1 = __float2half(p1);
            __half b2 = __float2half(p2), b3 = __float2half(p3);
            __half2 t01(b0, b1), t23(b2, b3);
            __half2 w01(__float2half(p0 - __half2float(b0)),
                        __float2half(p1 - __half2float(b1)));
            __half2 w23(__float2half(p2 - __half2float(b2)),
                        __float2half(p3 - __half2float(b3)));
            ph[ni][0] = *(uint32_t*)&t01;
            ph[ni][1] = *(uint32_t*)&t23;
            pl[ni][0] = *(uint32_t*)&w01;
            pl[ni][1] = *(uint32_t*)&w23;
        }
        rs0 += __shfl_xor_sync(0xffffffff, rs0, 1);
        rs0 += __shfl_xor_sync(0xffffffff, rs0, 2);
        rs1 += __shfl_xor_sync(0xffffffff, rs1, 1);
        rs1 += __shfl_xor_sync(0xffffffff, rs1, 2);
        l0 = l0 * sc0 + rs0;
        l1 = l1 * sc1 + rs1;

#pragma unroll
        for (int ni = 0; ni < 8; ++ni) {
            o[ni][0] *= sc0; o[ni][1] *= sc0;
            o[ni][2] *= sc1; o[ni][3] *= sc1;
        }

#pragma unroll
        for (int ks = 0; ks < 4; ++ks) {
            uint32_t vb[8][2];
#pragma unroll
            for (int ni = 0; ni < 8; ++ni) {
                const int base = (ni * 8 + tr) * SROW2 + ks * 16 + tc2;
                vb[ni][0] = *(const uint32_t*)(Vt + base);
                vb[ni][1] = *(const uint32_t*)(Vt + base + 8);
            }
#pragma unroll
            for (int ni = 0; ni < 8; ++ni)
                mma_f16(o[ni], ph[2*ks][0], ph[2*ks][1], ph[2*ks+1][0], ph[2*ks+1][1],
                        vb[ni][0], vb[ni][1]);
#pragma unroll
            for (int ni = 0; ni < 8; ++ni)
                mma_f16(o[ni], pl[2*ks][0], pl[2*ks][1], pl[2*ks+1][0], pl[2*ks+1][1],
                        vb[ni][0], vb[ni][1]);
        }
        __syncthreads();
    }

    const int b = bh >> 4, h = bh & 15;
    const float inv0 = 1.f / l0, inv1 = 1.f / l1;
    const size_t t0 = (size_t)(b * SEQ + i0) * D_MODEL + (size_t)h * HDIM;
    const size_t t1 = (size_t)(b * SEQ + i1) * D_MODEL + (size_t)h * HDIM;
#pragma unroll
    for (int ni = 0; ni < 8; ++ni) {
        const int c = ni * 8 + tc2;
        *(__half2*)(af + t0 + c) = __half2(__float2half(o[ni][0] * inv0),
                                           __float2half(o[ni][1] * inv0));
        *(__half2*)(af + t1 + c) = __half2(__float2half(o[ni][2] * inv1),
                                           __float2half(o[ni][3] * inv1));
    }
}

// ---- proj GEMM: fp16 1-term, 3-stage pipeline ---------------------------------
__global__ __launch_bounds__(256, 2)
void gemm_proj(const __half* __restrict__ A, const __half* __restrict__ W,
               const float* __restrict__ bias, float* __restrict__ C,
               int M, int N, int K)
{
    extern __shared__ __half smemh[];
    const int tid  = threadIdx.x;
    const int lane = tid & 31;
    const int wid  = tid >> 5;
    const int wm   = wid >> 2;
    const int wn   = wid & 3;
    const int tr   = lane >> 2;
    const int tc2  = (lane & 3) * 2;
    const int bm   = blockIdx.y * BM;
    const int bn   = blockIdx.x * BN;

    const uint32_t sbase = smem_u32(smemh);

    float acc[4][4][4];
#pragma unroll
    for (int i = 0; i < 4; ++i)
#pragma unroll
        for (int j = 0; j < 4; ++j)
#pragma unroll
            for (int r = 0; r < 4; ++r) acc[i][j][r] = 0.f;

    const __half* srcs[2] = { A, W };
    const int rowoff[2] = { bm, bn };

    auto load_stage = [&](int s, int k0) {
        const uint32_t st = sbase + (uint32_t)(s * GSTAGE_E * 2);
#pragma unroll
        for (int t = 0; t < 2; ++t) {
#pragma unroll
            for (int g2 = 0; g2 < 2; ++g2) {
                const int g = tid + g2 * 256;
                const int row = g >> 2, part = g & 3;
                const uint32_t dst = st + (uint32_t)(t * TILE_E + row * SROW + part * 8) * 2;
                const __half* src = srcs[t] + (size_t)(rowoff[t] + row) * K + k0 + part * 8;
                cp16(dst, src);
            }
        }
    };

    const int KCH = K / BK;
    load_stage(0, 0);
    CP_COMMIT();
    load_stage(1, BK);
    CP_COMMIT();

    int s = 0;
    for (int c = 0; c < KCH; ++c) {
        if (c + 2 < KCH) {
            const int sn = (s + 2 >= 3) ? s - 1 : s + 2;
            load_stage(sn, (c + 2) * BK);
            CP_COMMIT();
            CP_WAIT(2);
        } else if (c + 1 < KCH) {
            CP_WAIT(1);
        } else {
            CP_WAIT(0);
        }
        __syncthreads();

        const __half* stg = smemh + s * GSTAGE_E;
        const __half* Ah = stg;
        const __half* Bh = stg + TILE_E;

#pragma unroll
        for (int k0 = 0; k0 < BK; k0 += 16) {
            uint32_t ah[4][4], bh[4][2];
#pragma unroll
            for (int mi = 0; mi < 4; ++mi) {
                const int base = (wm * 64 + mi * 16 + tr) * SROW + k0 + tc2;
                ah[mi][0] = *(const uint32_t*)(Ah + base);
                ah[mi][1] = *(const uint32_t*)(Ah + base + 8 * SROW);
                ah[mi][2] = *(const uint32_t*)(Ah + base + 8);
                ah[mi][3] = *(const uint32_t*)(Ah + base + 8 * SROW + 8);
            }
#pragma unroll
            for (int ni = 0; ni < 4; ++ni) {
                const int base = (wn * 32 + ni * 8 + tr) * SROW + k0 + tc2;
                bh[ni][0] = *(const uint32_t*)(Bh + base);
                bh[ni][1] = *(const uint32_t*)(Bh + base + 8);
            }
#pragma unroll
            for (int mi = 0; mi < 4; ++mi)
#pragma unroll
                for (int ni = 0; ni < 4; ++ni)
                    mma_f16(acc[mi][ni], ah[mi][0], ah[mi][1], ah[mi][2], ah[mi][3],
                            bh[ni][0], bh[ni][1]);
        }
        __syncthreads();
        s = (s == 2) ? 0 : s + 1;
    }

#pragma unroll
    for (int mi = 0; mi < 4; ++mi) {
        const int r = bm + wm * 64 + mi * 16 + tr;
#pragma unroll
        for (int ni = 0; ni < 4; ++ni) {
            const int cidx = bn + wn * 32 + ni * 8 + tc2;
            const float b0 = bias[cidx], b1 = bias[cidx + 1];
            float2 v0 = make_float2(acc[mi][ni][0] + b0, acc[mi][ni][1] + b1);
            float2 v1 = make_float2(acc[mi][ni][2] + b0, acc[mi][ni][3] + b1);
            *(float2*)(C + (size_t)r * N + cidx)       = v0;
            *(float2*)(C + (size_t)(r + 8) * N + cidx) = v1;
        }
    }
}

// ---------------------------------------------------------------------------
extern "C" void kernel_launch(void* const* d_in, const int* in_sizes, int n_in,
                              void* d_out, int out_size)
{
    const float* x      = (const float*)d_in[0];
    const float* w_qkv  = (const float*)d_in[1];
    const float* b_qkv  = (const float*)d_in[2];
    const float* w_proj = (const float*)d_in[3];
    const float* b_proj = (const float*)d_in[4];
    float* out = (float*)d_out;

    __half *xf, *wq, *wph, *af, *q, *k, *vt;
    cudaGetSymbolAddress((void**)&xf, g_xf);
    cudaGetSymbolAddress((void**)&wq, g_wq);
    cudaGetSymbolAddress((void**)&wph, g_wph);
    cudaGetSymbolAddress((void**)&q, g_q);
    cudaGetSymbolAddress((void**)&k, g_k);
    cudaGetSymbolAddress((void**)&vt, g_vt);
    cudaGetSymbolAddress((void**)&af, g_af);

    cudaFuncSetAttribute(gemm_qkv,
                         cudaFuncAttributeMaxDynamicSharedMemorySize, GSMEM_SZ);
    cudaFuncSetAttribute(swa_tensor,
                         cudaFuncAttributeMaxDynamicSharedMemorySize, SWA_SMEM);
    cudaFuncSetAttribute(gemm_proj,
                         cudaFuncAttributeMaxDynamicSharedMemorySize, GSMEM_SZ);

    // fused input conversion (one launch)
    cvt_all<<<(N4X + N4Q + N4P) / 256, 256>>>(
        (const float4*)x, (const float4*)w_qkv, (const float4*)w_proj,
        xf, wq, wph);

    // 1) QKV projection (fp16 1-term, 3-stage) -> per-head fp16 Q,K + V^T
    gemm_qkv<<<dim3(QKV_LD / BN, MTOT / BM), 256, GSMEM_SZ>>>(
        xf, wq, b_qkv, q, k, vt);

    // 2) sliding-window attention -> plain fp16
    swa_tensor<<<dim3(SEQ / 64, BHTOT), 128, SWA_SMEM>>>(q, k, vt, af);

    // 3) output projection (fp16 1-term, 3-stage)
    gemm_proj<<<dim3(D_MODEL / BN, MTOT / BM), 256, GSMEM_SZ>>>(
        af, wph, b_proj, out, MTOT, D_MODEL, D_MODEL);
}